// round 9
// baseline (speedup 1.0000x reference)
#include <cuda_runtime.h>
#include <cuda_bf16.h>
#include <cstdint>

// NT=32, HS=64, WS=64 (K), CL=96 (l/j), OD=128 (o), G=8
// b = nt*64 + hs in [0,2048). One problem per CTA.

__device__ __align__(16) float g_scratch[2048 * 64 * 96];  // scr[b*6144 + d*96 + cl]

__device__ __forceinline__ float ex2f(float x) {
    float r;
    asm("ex2.approx.f32 %0, %1;" : "=f"(r) : "f"(x));
    return r;
}
__device__ __forceinline__ float rcpf(float x) {
    float r;
    asm("rcp.approx.f32 %0, %1;" : "=f"(r) : "f"(x));
    return r;
}

__device__ __forceinline__ void mma_k16(float* d, const uint32_t* a,
                                        uint32_t b0, uint32_t b1) {
    asm volatile(
        "mma.sync.aligned.m16n8k16.row.col.f32.bf16.bf16.f32 "
        "{%0,%1,%2,%3}, {%4,%5,%6,%7}, {%8,%9}, {%0,%1,%2,%3};"
        : "+f"(d[0]), "+f"(d[1]), "+f"(d[2]), "+f"(d[3])
        : "r"(a[0]), "r"(a[1]), "r"(a[2]), "r"(a[3]), "r"(b0), "r"(b1));
}
__device__ __forceinline__ void mma_k8(float* d, uint32_t a0, uint32_t a1,
                                       uint32_t b0) {
    asm volatile(
        "mma.sync.aligned.m16n8k8.row.col.f32.bf16.bf16.f32 "
        "{%0,%1,%2,%3}, {%4,%5}, {%6}, {%0,%1,%2,%3};"
        : "+f"(d[0]), "+f"(d[1]), "+f"(d[2]), "+f"(d[3])
        : "r"(a0), "r"(a1), "r"(b0));
}

__device__ __forceinline__ uint32_t bpack(float lo, float hi) {
    __nv_bfloat162 t = __float22bfloat162_rn(make_float2(lo, hi));
    return *(uint32_t*)&t;
}
__device__ __forceinline__ float blo(uint32_t hw) {
    return __uint_as_float(hw << 16);
}
__device__ __forceinline__ float bhi(uint32_t hw) {
    return __uint_as_float(hw & 0xFFFF0000u);
}

// split float4 into bf16-high / bf16-low, store 8B to each buffer
__device__ __forceinline__ void split8(char* hb, char* lb, uint32_t off, float4 v) {
    __nv_bfloat162 h0 = __float22bfloat162_rn(make_float2(v.x, v.y));
    __nv_bfloat162 h1 = __float22bfloat162_rn(make_float2(v.z, v.w));
    float2 f0 = __bfloat1622float2(h0), f1 = __bfloat1622float2(h1);
    __nv_bfloat162 l0 = __float22bfloat162_rn(make_float2(v.x - f0.x, v.y - f0.y));
    __nv_bfloat162 l1 = __float22bfloat162_rn(make_float2(v.z - f1.x, v.w - f1.y));
    uint2 hv, lv;
    hv.x = *(uint32_t*)&h0; hv.y = *(uint32_t*)&h1;
    lv.x = *(uint32_t*)&l0; lv.y = *(uint32_t*)&l1;
    *(uint2*)(hb + off) = hv;
    *(uint2*)(lb + off) = lv;
}

// ---------------- shared memory layout ----------------
// Phase 1 (QKV GEMM operands; rows stride 144B). Dead after MMA barrier.
#define OFF_AH 0        // Wh: 128 x 144B
#define OFF_AL 18432    // Wl
#define OFF_XH 36864    // Xh: 96 x 144B
#define OFF_XL 50688    // Xl              (end 64512)
// Phase 2: per-warp buffers (aliasing phase 1), byte base w*PWB:
//   QAH/QAL: q A-frag pairs  [96 i][4 cp] bf16x2  (cp 2,3 zero)
//   KBH/KBL: k B-frag pairs  [96 j][4 cp] bf16x2  (cp 2,3 zero)
//   VH/VL:   v B-frag pairs  [8 c][48 jp] bf16x2, row stride 208B
//   QS:      fp32 BN'd q,k   [96 l][8 c], row stride 40B
#define PWB    13312
#define O_QAH  0
#define O_QAL  1536
#define O_KBH  3072
#define O_KBL  4608
#define O_VH   6144
#define O_VL   7808
#define O_QS   9472     // 96*40 = 3840, end 13312
// coefficients, float indices from smem base (beyond byte 106496):
#define CAQ 26624
#define CBQ 26752
#define CAS 26880
#define CAO 26888
#define CBO 26952
#define SMEM_BYTES 108064

extern "C" __global__ void __launch_bounds__(256, 2)
attn_fused_kernel(const float* __restrict__ x, const float* __restrict__ w_qkv,
                  const float* __restrict__ qg, const float* __restrict__ qb,
                  const float* __restrict__ qm, const float* __restrict__ qv,
                  const float* __restrict__ sg, const float* __restrict__ sb,
                  const float* __restrict__ smn, const float* __restrict__ svr,
                  const float* __restrict__ og, const float* __restrict__ ob,
                  const float* __restrict__ om, const float* __restrict__ ov) {
    extern __shared__ __align__(16) char smemc[];
    float* smem = (float*)smemc;
    const int tid  = threadIdx.x;
    const int lane = tid & 31;
    const int w    = tid >> 5;
    const int b    = blockIdx.x;
    const int nt   = b >> 6;
    const int hs   = b & 63;
    const int r0   = lane >> 2;   // 0..7
    const int m4   = lane & 3;    // 0..3

    // ---- BN coefficient precompute ----
    if (tid < 128) {
        float a = qg[tid] * rsqrtf(qv[tid] + 1e-5f);
        smem[CAQ + tid] = a;
        smem[CBQ + tid] = qb[tid] - qm[tid] * a;
    }
    if (tid < 64) {
        float a = og[tid] * rsqrtf(ov[tid] + 1e-5f);
        smem[CAO + tid] = a;
        smem[CBO + tid] = ob[tid] - om[tid] * a;
    }
    if (tid < 8) {
        smem[CAS + tid] = sg[tid] * rsqrtf(svr[tid] + 1e-5f);
        (void)sb; (void)smn;  // sim BN bias cancels inside softmax
    }

    // ---- operand prep: W split (A, 128 rows(o) x 64 bf16(i)) ----
#pragma unroll
    for (int u = 0; u < 8; u++) {
        int idx4 = tid + 256 * u;
        int o = idx4 >> 4, i4 = idx4 & 15;
        float4 v = *(const float4*)(w_qkv + idx4 * 4);
        split8(smemc + OFF_AH, smemc + OFF_AL, o * 144 + i4 * 8, v);
    }
    // ---- operand prep: X split (B, 96 rows(l) x 64 bf16(i)) ----
    {
        const float* xbase = x + (size_t)nt * 393216 + (size_t)hs * 64;
#pragma unroll
        for (int u = 0; u < 6; u++) {
            int idx = tid + 256 * u;
            int i4 = idx & 15, l = idx >> 4;
            float4 v = *(const float4*)(xbase + (size_t)l * 4096 + i4 * 4);
            split8(smemc + OFF_XH, smemc + OFF_XL, l * 144 + i4 * 8, v);
        }
    }
    __syncthreads();

    // ---- tensor-core QKV GEMM: warp w owns rows o in [16w, 16w+16) ----
    float d[12][4];
#pragma unroll
    for (int p = 0; p < 12; p++)
#pragma unroll
        for (int q = 0; q < 4; q++) d[p][q] = 0.f;
    {
        const int qk2 = m4 * 4;   // byte offset of k-pair
        uint32_t ah[4][4];
#pragma unroll
        for (int k = 0; k < 4; k++) {
            uint32_t off = (uint32_t)(16 * w + r0) * 144 + 32 * k + qk2;
            ah[k][0] = *(const uint32_t*)(smemc + OFF_AH + off);
            ah[k][1] = *(const uint32_t*)(smemc + OFF_AH + off + 8 * 144);
            ah[k][2] = *(const uint32_t*)(smemc + OFF_AH + off + 16);
            ah[k][3] = *(const uint32_t*)(smemc + OFF_AH + off + 8 * 144 + 16);
        }
#pragma unroll
        for (int k = 0; k < 4; k++)
#pragma unroll
            for (int p = 0; p < 6; p++) {
                uint32_t boff = (uint32_t)(16 * p + r0) * 144 + 32 * k + qk2;
                uint32_t b0 = *(const uint32_t*)(smemc + OFF_XH + boff);
                uint32_t b1 = *(const uint32_t*)(smemc + OFF_XH + boff + 16);
                uint32_t b2 = *(const uint32_t*)(smemc + OFF_XH + boff + 8 * 144);
                uint32_t b3 = *(const uint32_t*)(smemc + OFF_XH + boff + 8 * 144 + 16);
                mma_k16(d[2 * p],     ah[k], b0, b1);
                mma_k16(d[2 * p + 1], ah[k], b2, b3);
            }
#pragma unroll
        for (int k = 0; k < 4; k++)
#pragma unroll
            for (int p = 0; p < 6; p++) {
                uint32_t boff = (uint32_t)(16 * p + r0) * 144 + 32 * k + qk2;
                uint32_t b0 = *(const uint32_t*)(smemc + OFF_XL + boff);
                uint32_t b1 = *(const uint32_t*)(smemc + OFF_XL + boff + 16);
                uint32_t b2 = *(const uint32_t*)(smemc + OFF_XL + boff + 8 * 144);
                uint32_t b3 = *(const uint32_t*)(smemc + OFF_XL + boff + 8 * 144 + 16);
                mma_k16(d[2 * p],     ah[k], b0, b1);
                mma_k16(d[2 * p + 1], ah[k], b2, b3);
            }
#pragma unroll
        for (int k = 0; k < 4; k++) {
            uint32_t off = (uint32_t)(16 * w + r0) * 144 + 32 * k + qk2;
            uint32_t al[4];
            al[0] = *(const uint32_t*)(smemc + OFF_AL + off);
            al[1] = *(const uint32_t*)(smemc + OFF_AL + off + 8 * 144);
            al[2] = *(const uint32_t*)(smemc + OFF_AL + off + 16);
            al[3] = *(const uint32_t*)(smemc + OFF_AL + off + 8 * 144 + 16);
#pragma unroll
            for (int p = 0; p < 6; p++) {
                uint32_t boff = (uint32_t)(16 * p + r0) * 144 + 32 * k + qk2;
                uint32_t b0 = *(const uint32_t*)(smemc + OFF_XH + boff);
                uint32_t b1 = *(const uint32_t*)(smemc + OFF_XH + boff + 16);
                uint32_t b2 = *(const uint32_t*)(smemc + OFF_XH + boff + 8 * 144);
                uint32_t b3 = *(const uint32_t*)(smemc + OFF_XH + boff + 8 * 144 + 16);
                mma_k8(d[2 * p],     al[0], al[1], b0);  // k8: first half
                mma_k8(d[2 * p],     al[2], al[3], b1);  // k8: second half
                mma_k8(d[2 * p + 1], al[0], al[1], b2);
                mma_k8(d[2 * p + 1], al[2], al[3], b3);
            }
        }
    }
    __syncthreads();   // operand reads done; per-warp buffers may alias now

    char* wb = smemc + w * PWB;

    // ---- epilogue: BN; q,k -> QS fp32; v -> VH/VL bf16-split (frag layout) ----
    {
        float aqk = smem[CAQ + 16 * w + r0],     bqk = smem[CBQ + 16 * w + r0];
        float aqv = smem[CAQ + 16 * w + 8 + r0], bqv = smem[CBQ + 16 * w + 8 + r0];
#pragma unroll
        for (int p = 0; p < 12; p++) {
            int l0 = 8 * p + 2 * m4;
            *(float*)(wb + O_QS + l0 * 40 + r0 * 4)       = d[p][0] * aqk + bqk;
            *(float*)(wb + O_QS + (l0 + 1) * 40 + r0 * 4) = d[p][1] * aqk + bqk;
            float vb0 = d[p][2] * aqv + bqv;
            float vb1 = d[p][3] * aqv + bqv;
            uint32_t hv = bpack(vb0, vb1);
            uint32_t lv = bpack(vb0 - blo(hv), vb1 - bhi(hv));
            uint32_t voff = (uint32_t)r0 * 208 + (4 * p + m4) * 4;
            *(uint32_t*)(wb + O_VH + voff) = hv;
            *(uint32_t*)(wb + O_VL + voff) = lv;
        }
    }
    __syncwarp();

    // ---- repack q,k into fragment-layout bf16 pairs (pairs along c) ----
    {
        const float sc = smem[CAS + w] * 1.4426950408889634f;  // ag/ln2
#pragma unroll
        for (int u = 0; u < 3; u++) {
            int i = lane + 32 * u;
            const char* qs = wb + O_QS + i * 40;
            // q: cols 0..3, scaled
            float2 q01 = *(const float2*)(qs);
            float2 q23 = *(const float2*)(qs + 8);
            float a0 = q01.x * sc, a1 = q01.y * sc;
            float a2 = q23.x * sc, a3 = q23.y * sc;
            uint32_t h0 = bpack(a0, a1), h1 = bpack(a2, a3);
            *(uint32_t*)(wb + O_QAH + i * 16)     = h0;
            *(uint32_t*)(wb + O_QAH + i * 16 + 4) = h1;
            *(uint64_t*)(wb + O_QAH + i * 16 + 8) = 0ull;
            *(uint32_t*)(wb + O_QAL + i * 16)     = bpack(a0 - blo(h0), a1 - bhi(h0));
            *(uint32_t*)(wb + O_QAL + i * 16 + 4) = bpack(a2 - blo(h1), a3 - bhi(h1));
            *(uint64_t*)(wb + O_QAL + i * 16 + 8) = 0ull;
            // k: cols 4..7
            float2 k01 = *(const float2*)(qs + 16);
            float2 k23 = *(const float2*)(qs + 24);
            uint32_t kh0 = bpack(k01.x, k01.y), kh1 = bpack(k23.x, k23.y);
            *(uint32_t*)(wb + O_KBH + i * 16)     = kh0;
            *(uint32_t*)(wb + O_KBH + i * 16 + 4) = kh1;
            *(uint64_t*)(wb + O_KBH + i * 16 + 8) = 0ull;
            *(uint32_t*)(wb + O_KBL + i * 16)     = bpack(k01.x - blo(kh0), k01.y - bhi(kh0));
            *(uint32_t*)(wb + O_KBL + i * 16 + 4) = bpack(k23.x - blo(kh1), k23.y - bhi(kh1));
            *(uint64_t*)(wb + O_KBL + i * 16 + 8) = 0ull;
        }
    }
    __syncwarp();

    // ---- HMMA attention: per m-tile t, stream over 12 j-chunks ----
    {
        float* scr = &g_scratch[(size_t)b * 6144];
        const int d0 = 8 * w + 2 * m4;
        const float ao0 = smem[CAO + d0],     bo0 = smem[CBO + d0];
        const float ao1 = smem[CAO + d0 + 1], bo1 = smem[CBO + d0 + 1];

#pragma unroll 1
        for (int t = 0; t < 6; t++) {
            uint32_t qoff = (uint32_t)(16 * t + r0) * 16 + m4 * 4;
            uint32_t qh0 = *(const uint32_t*)(wb + O_QAH + qoff);
            uint32_t qh1 = *(const uint32_t*)(wb + O_QAH + qoff + 8 * 16);
            uint32_t ql0 = *(const uint32_t*)(wb + O_QAL + qoff);
            uint32_t ql1 = *(const uint32_t*)(wb + O_QAL + qoff + 8 * 16);

            float dsv[4] = {0.f, 0.f, 0.f, 0.f};
            float s_lo = 0.f, s_hi = 0.f;

#pragma unroll 4
            for (int ch = 0; ch < 12; ch++) {
                uint32_t koff = (uint32_t)(8 * ch + r0) * 16 + m4 * 4;
                uint32_t kh = *(const uint32_t*)(wb + O_KBH + koff);
                uint32_t kl = *(const uint32_t*)(wb + O_KBL + koff);
                uint32_t voff = (uint32_t)r0 * 208 + (4 * ch + m4) * 4;
                uint32_t vh = *(const uint32_t*)(wb + O_VH + voff);
                uint32_t vl = *(const uint32_t*)(wb + O_VL + voff);

                float S[4] = {0.f, 0.f, 0.f, 0.f};
                mma_k8(S, qh0, qh1, kh);
                mma_k8(S, ql0, ql1, kh);
                mma_k8(S, qh0, qh1, kl);

                float e0 = ex2f(S[0]), e1 = ex2f(S[1]);
                float e2 = ex2f(S[2]), e3 = ex2f(S[3]);
                s_lo += e0 + e1;
                s_hi += e2 + e3;
                uint32_t sh0 = bpack(e0, e1), sh1 = bpack(e2, e3);
                uint32_t sl0 = bpack(e0 - blo(sh0), e1 - bhi(sh0));
                uint32_t sl1 = bpack(e2 - blo(sh1), e3 - bhi(sh1));

                mma_k8(dsv, sh0, sh1, vh);
                mma_k8(dsv, sl0, sl1, vh);
                mma_k8(dsv, sh0, sh1, vl);
            }

            s_lo += __shfl_xor_sync(0xffffffffu, s_lo, 1);
            s_lo += __shfl_xor_sync(0xffffffffu, s_lo, 2);
            s_hi += __shfl_xor_sync(0xffffffffu, s_hi, 1);
            s_hi += __shfl_xor_sync(0xffffffffu, s_hi, 2);
            float rl = rcpf(s_lo), rh = rcpf(s_hi);

            int i0 = 16 * t + r0;
            scr[d0 * 96 + i0]           = dsv[0] * rl * ao0 + bo0;
            scr[(d0 + 1) * 96 + i0]     = dsv[1] * rl * ao1 + bo1;
            scr[d0 * 96 + i0 + 8]       = dsv[2] * rh * ao0 + bo0;
            scr[(d0 + 1) * 96 + i0 + 8] = dsv[3] * rh * ao1 + bo1;
        }
    }
}

// Permute scr[(nt*64+hs)*6144 + d*96 + cl] -> out[((nt*96+cl)*64 + d)*64 + hs]
extern "C" __global__ void __launch_bounds__(256)
attn_transpose_kernel(float* __restrict__ out) {
    __shared__ float tile[64 * 97];
    const int nt = blockIdx.x >> 6;
    const int d  = blockIdx.x & 63;

    const float* src = g_scratch + (size_t)nt * 393216 + (size_t)d * 96;
#pragma unroll
    for (int u = 0; u < 6; u++) {
        int idx = threadIdx.x + 256 * u;
        int h = idx / 24, c4 = idx % 24;
        float4 v = *(const float4*)(src + (size_t)h * 6144 + c4 * 4);
        float* dst = &tile[h * 97 + c4 * 4];
        dst[0] = v.x; dst[1] = v.y; dst[2] = v.z; dst[3] = v.w;
    }
    __syncthreads();

    float* dst = out + (size_t)nt * 393216 + (size_t)d * 64;
#pragma unroll
    for (int u = 0; u < 24; u++) {
        int idx = threadIdx.x + 256 * u;
        int cl = idx >> 6, h = idx & 63;
        dst[(size_t)cl * 4096 + h] = tile[h * 97 + cl];
    }
}

extern "C" void kernel_launch(void* const* d_in, const int* in_sizes, int n_in,
                              void* d_out, int out_size) {
    const float* x   = (const float*)d_in[0];
    const float* wq  = (const float*)d_in[1];
    const float* qg  = (const float*)d_in[2];
    const float* qb  = (const float*)d_in[3];
    const float* qm  = (const float*)d_in[4];
    const float* qv  = (const float*)d_in[5];
    const float* sg  = (const float*)d_in[6];
    const float* sb  = (const float*)d_in[7];
    const float* smn = (const float*)d_in[8];
    const float* svr = (const float*)d_in[9];
    const float* og  = (const float*)d_in[10];
    const float* ob  = (const float*)d_in[11];
    const float* om  = (const float*)d_in[12];
    const float* ov  = (const float*)d_in[13];
    float* out = (float*)d_out;

    cudaFuncSetAttribute(attn_fused_kernel,
                         cudaFuncAttributeMaxDynamicSharedMemorySize, SMEM_BYTES);

    attn_fused_kernel<<<2048, 256, SMEM_BYTES>>>(x, wq, qg, qb, qm, qv, sg, sb,
                                                 smn, svr, og, ob, om, ov);
    attn_transpose_kernel<<<2048, 256>>>(out);
}

// round 10
// speedup vs baseline: 1.2100x; 1.2100x over previous
#include <cuda_runtime.h>
#include <cuda_bf16.h>
#include <cuda_fp16.h>
#include <cstdint>

// NT=32, HS=64, WS=64 (K), CL=96 (l/j), OD=128 (o), G=8
// b = nt*64 + hs in [0,2048). One problem per CTA.

__device__ __align__(16) __half g_scratch[2048 * 64 * 96];  // scr[b*6144 + d*96 + cl]

__device__ __forceinline__ float ex2f(float x) {
    float r;
    asm("ex2.approx.f32 %0, %1;" : "=f"(r) : "f"(x));
    return r;
}
__device__ __forceinline__ float rcpf(float x) {
    float r;
    asm("rcp.approx.f32 %0, %1;" : "=f"(r) : "f"(x));
    return r;
}

__device__ __forceinline__ void mma_k16(float* d, const uint32_t* a,
                                        uint32_t b0, uint32_t b1) {
    asm volatile(
        "mma.sync.aligned.m16n8k16.row.col.f32.bf16.bf16.f32 "
        "{%0,%1,%2,%3}, {%4,%5,%6,%7}, {%8,%9}, {%0,%1,%2,%3};"
        : "+f"(d[0]), "+f"(d[1]), "+f"(d[2]), "+f"(d[3])
        : "r"(a[0]), "r"(a[1]), "r"(a[2]), "r"(a[3]), "r"(b0), "r"(b1));
}

__device__ __forceinline__ uint32_t bpack(float lo, float hi) {
    __nv_bfloat162 t = __float22bfloat162_rn(make_float2(lo, hi));
    return *(uint32_t*)&t;
}
__device__ __forceinline__ float blo(uint32_t hw) {
    return __uint_as_float(hw << 16);
}
__device__ __forceinline__ float bhi(uint32_t hw) {
    return __uint_as_float(hw & 0xFFFF0000u);
}

// split float4 into bf16-high / bf16-low, store 8B to each buffer
__device__ __forceinline__ void split8(char* hb, char* lb, uint32_t off, float4 v) {
    __nv_bfloat162 h0 = __float22bfloat162_rn(make_float2(v.x, v.y));
    __nv_bfloat162 h1 = __float22bfloat162_rn(make_float2(v.z, v.w));
    float2 f0 = __bfloat1622float2(h0), f1 = __bfloat1622float2(h1);
    __nv_bfloat162 l0 = __float22bfloat162_rn(make_float2(v.x - f0.x, v.y - f0.y));
    __nv_bfloat162 l1 = __float22bfloat162_rn(make_float2(v.z - f1.x, v.w - f1.y));
    uint2 hv, lv;
    hv.x = *(uint32_t*)&h0; hv.y = *(uint32_t*)&h1;
    lv.x = *(uint32_t*)&l0; lv.y = *(uint32_t*)&l1;
    *(uint2*)(hb + off) = hv;
    *(uint2*)(lb + off) = lv;
}

// ---------------- shared memory layout ----------------
// Phase 1 (QKV GEMM operands; rows stride 144B). Dead after MMA barrier.
#define OFF_AH 0        // Wh: 128 x 144B
#define OFF_AL 18432    // Wl
#define OFF_XH 36864    // Xh: 96 x 144B
#define OFF_XL 50688    // Xl              (end 64512)
// Phase 2: per-warp attention buffers (alias phase 1), base w*PWB:
//   Q: 96 rows x 48B; 16 bf16 slots = [qh(c0..3) | ql(c0..3) | qh(c0..3) | 0]
//   K: 96 rows x 48B; slots = [kh | kh | kl | 0]
//   VH/VL: 8 c-rows x 208B of bf16 over j (96 used)
#define PWB  12544
#define O_Q  0
#define O_K  4608
#define O_VH 9216
#define O_VL 10880      // end 12544; x8 warps = 100352
// coefficients, float indices from smem base (byte 100352+):
#define CAQ 25088
#define CBQ 25216
#define CAS 25344
#define CAO 25352
#define CBO 25416
#define SMEM_BYTES 101920

extern "C" __global__ void __launch_bounds__(256, 2)
attn_fused_kernel(const float* __restrict__ x, const float* __restrict__ w_qkv,
                  const float* __restrict__ qg, const float* __restrict__ qb,
                  const float* __restrict__ qm, const float* __restrict__ qv,
                  const float* __restrict__ sg, const float* __restrict__ sb,
                  const float* __restrict__ smn, const float* __restrict__ svr,
                  const float* __restrict__ og, const float* __restrict__ ob,
                  const float* __restrict__ om, const float* __restrict__ ov) {
    extern __shared__ __align__(16) char smemc[];
    float* smem = (float*)smemc;
    const int tid  = threadIdx.x;
    const int lane = tid & 31;
    const int w    = tid >> 5;
    const int b    = blockIdx.x;
    const int nt   = b >> 6;
    const int hs   = b & 63;
    const int r0   = lane >> 2;   // 0..7
    const int m4   = lane & 3;    // 0..3

    // ---- BN coefficient precompute ----
    if (tid < 128) {
        float a = qg[tid] * rsqrtf(qv[tid] + 1e-5f);
        smem[CAQ + tid] = a;
        smem[CBQ + tid] = qb[tid] - qm[tid] * a;
    }
    if (tid < 64) {
        float a = og[tid] * rsqrtf(ov[tid] + 1e-5f);
        smem[CAO + tid] = a;
        smem[CBO + tid] = ob[tid] - om[tid] * a;
    }
    if (tid < 8) {
        smem[CAS + tid] = sg[tid] * rsqrtf(svr[tid] + 1e-5f);
        (void)sb; (void)smn;  // sim BN bias cancels inside softmax
    }

    // ---- operand prep: W split (A, 128 rows(o) x 64 bf16(i)) ----
#pragma unroll
    for (int u = 0; u < 8; u++) {
        int idx4 = tid + 256 * u;
        int o = idx4 >> 4, i4 = idx4 & 15;
        float4 v = *(const float4*)(w_qkv + idx4 * 4);
        split8(smemc + OFF_AH, smemc + OFF_AL, o * 144 + i4 * 8, v);
    }
    // ---- operand prep: X split (B, 96 rows(l) x 64 bf16(i)) ----
    {
        const float* xbase = x + (size_t)nt * 393216 + (size_t)hs * 64;
#pragma unroll
        for (int u = 0; u < 6; u++) {
            int idx = tid + 256 * u;
            int i4 = idx & 15, l = idx >> 4;
            float4 v = *(const float4*)(xbase + (size_t)l * 4096 + i4 * 4);
            split8(smemc + OFF_XH, smemc + OFF_XL, l * 144 + i4 * 8, v);
        }
    }
    __syncthreads();

    // ---- tensor-core QKV GEMM: warp w owns rows o in [16w, 16w+16) ----
    float d[12][4];
#pragma unroll
    for (int p = 0; p < 12; p++)
#pragma unroll
        for (int q = 0; q < 4; q++) d[p][q] = 0.f;
    {
        const int qk2 = m4 * 4;
        uint32_t ah[4][4];
#pragma unroll
        for (int k = 0; k < 4; k++) {
            uint32_t off = (uint32_t)(16 * w + r0) * 144 + 32 * k + qk2;
            ah[k][0] = *(const uint32_t*)(smemc + OFF_AH + off);
            ah[k][1] = *(const uint32_t*)(smemc + OFF_AH + off + 8 * 144);
            ah[k][2] = *(const uint32_t*)(smemc + OFF_AH + off + 16);
            ah[k][3] = *(const uint32_t*)(smemc + OFF_AH + off + 8 * 144 + 16);
        }
#pragma unroll
        for (int k = 0; k < 4; k++)
#pragma unroll
            for (int p = 0; p < 6; p++) {
                uint32_t boff = (uint32_t)(16 * p + r0) * 144 + 32 * k + qk2;
                uint32_t b0 = *(const uint32_t*)(smemc + OFF_XH + boff);
                uint32_t b1 = *(const uint32_t*)(smemc + OFF_XH + boff + 16);
                uint32_t b2 = *(const uint32_t*)(smemc + OFF_XH + boff + 8 * 144);
                uint32_t b3 = *(const uint32_t*)(smemc + OFF_XH + boff + 8 * 144 + 16);
                mma_k16(d[2 * p],     ah[k], b0, b1);
                mma_k16(d[2 * p + 1], ah[k], b2, b3);
            }
#pragma unroll
        for (int k = 0; k < 4; k++)
#pragma unroll
            for (int p = 0; p < 6; p++) {
                uint32_t boff = (uint32_t)(16 * p + r0) * 144 + 32 * k + qk2;
                uint32_t b0 = *(const uint32_t*)(smemc + OFF_XL + boff);
                uint32_t b1 = *(const uint32_t*)(smemc + OFF_XL + boff + 16);
                uint32_t b2 = *(const uint32_t*)(smemc + OFF_XL + boff + 8 * 144);
                uint32_t b3 = *(const uint32_t*)(smemc + OFF_XL + boff + 8 * 144 + 16);
                mma_k16(d[2 * p],     ah[k], b0, b1);
                mma_k16(d[2 * p + 1], ah[k], b2, b3);
            }
#pragma unroll
        for (int k = 0; k < 4; k++) {
            uint32_t off = (uint32_t)(16 * w + r0) * 144 + 32 * k + qk2;
            uint32_t al[4];
            al[0] = *(const uint32_t*)(smemc + OFF_AL + off);
            al[1] = *(const uint32_t*)(smemc + OFF_AL + off + 8 * 144);
            al[2] = *(const uint32_t*)(smemc + OFF_AL + off + 16);
            al[3] = *(const uint32_t*)(smemc + OFF_AL + off + 8 * 144 + 16);
#pragma unroll
            for (int p = 0; p < 6; p++) {
                uint32_t boff = (uint32_t)(16 * p + r0) * 144 + 32 * k + qk2;
                uint32_t b0 = *(const uint32_t*)(smemc + OFF_XH + boff);
                uint32_t b1 = *(const uint32_t*)(smemc + OFF_XH + boff + 16);
                uint32_t b2 = *(const uint32_t*)(smemc + OFF_XH + boff + 8 * 144);
                uint32_t b3 = *(const uint32_t*)(smemc + OFF_XH + boff + 8 * 144 + 16);
                mma_k16(d[2 * p],     al, b0, b1);
                mma_k16(d[2 * p + 1], al, b2, b3);
            }
        }
    }
    __syncthreads();   // operand reads done; per-warp buffers may alias now

    char* wb = smemc + w * PWB;

    // ---- zero the k-slot padding (bytes 24..31 of each Q/K row) ----
#pragma unroll
    for (int u = 0; u < 3; u++) {
        int row = lane + 32 * u;
        *(uint64_t*)(wb + O_Q + row * 48 + 24) = 0ull;
        *(uint64_t*)(wb + O_K + row * 48 + 24) = 0ull;
    }

    // ---- epilogue: BN; q/k/v into attention operand buffers ----
    {
        const float sc = smem[CAS + w] * 1.4426950408889634f;  // ag/ln2
        const int o = 16 * w + r0;
        float A, B;
        if (r0 < 4) { A = smem[CAQ + o] * sc; B = smem[CBQ + o] * sc; }
        else        { A = smem[CAQ + o];      B = smem[CBQ + o]; }
        const float av = smem[CAQ + o + 8], bv = smem[CBQ + o + 8];
#pragma unroll
        for (int p = 0; p < 12; p++) {
            int l0 = 8 * p + 2 * m4;
            float v0 = d[p][0] * A + B, v1 = d[p][1] * A + B;
            __nv_bfloat16 h0 = __float2bfloat16_rn(v0);
            __nv_bfloat16 h1 = __float2bfloat16_rn(v1);
            __nv_bfloat16 g0 = __float2bfloat16_rn(v0 - __bfloat162float(h0));
            __nv_bfloat16 g1 = __float2bfloat16_rn(v1 - __bfloat162float(h1));
            if (r0 < 4) {
                int c = r0;
                char* q0p = wb + O_Q + l0 * 48;
                char* q1p = q0p + 48;
                *(__nv_bfloat16*)(q0p + 2 * c)       = h0;
                *(__nv_bfloat16*)(q0p + 2 * (8 + c)) = h0;
                *(__nv_bfloat16*)(q0p + 2 * (4 + c)) = g0;
                *(__nv_bfloat16*)(q1p + 2 * c)       = h1;
                *(__nv_bfloat16*)(q1p + 2 * (8 + c)) = h1;
                *(__nv_bfloat16*)(q1p + 2 * (4 + c)) = g1;
            } else {
                int c = r0 - 4;
                char* k0p = wb + O_K + l0 * 48;
                char* k1p = k0p + 48;
                *(__nv_bfloat16*)(k0p + 2 * c)       = h0;
                *(__nv_bfloat16*)(k0p + 2 * (4 + c)) = h0;
                *(__nv_bfloat16*)(k0p + 2 * (8 + c)) = g0;
                *(__nv_bfloat16*)(k1p + 2 * c)       = h1;
                *(__nv_bfloat16*)(k1p + 2 * (4 + c)) = h1;
                *(__nv_bfloat16*)(k1p + 2 * (8 + c)) = g1;
            }
            float vb0 = d[p][2] * av + bv, vb1 = d[p][3] * av + bv;
            uint32_t hv = bpack(vb0, vb1);
            uint32_t lv = bpack(vb0 - blo(hv), vb1 - bhi(hv));
            *(uint32_t*)(wb + O_VH + r0 * 208 + l0 * 2) = hv;
            *(uint32_t*)(wb + O_VL + r0 * 208 + l0 * 2) = lv;
        }
    }
    __syncwarp();   // buffers are warp-private

    // ---- HMMA attention: all-k16, split folded into k slots ----
    {
        __half* scr = &g_scratch[(size_t)b * 6144];
        const int d0 = 8 * w + 2 * m4;
        const float ao0 = smem[CAO + d0],     bo0 = smem[CBO + d0];
        const float ao1 = smem[CAO + d0 + 1], bo1 = smem[CBO + d0 + 1];

#pragma unroll 1
        for (int t = 0; t < 6; t++) {
            uint32_t qa[4];
            {
                uint32_t qoff = (uint32_t)(16 * t + r0) * 48 + 4 * m4;
                qa[0] = *(const uint32_t*)(wb + O_Q + qoff);
                qa[1] = *(const uint32_t*)(wb + O_Q + qoff + 8 * 48);
                qa[2] = *(const uint32_t*)(wb + O_Q + qoff + 16);
                qa[3] = *(const uint32_t*)(wb + O_Q + qoff + 8 * 48 + 16);
            }
            float accA[4] = {0.f, 0.f, 0.f, 0.f};
            float accB[4] = {0.f, 0.f, 0.f, 0.f};
            float s_lo = 0.f, s_hi = 0.f;

#pragma unroll 2
            for (int blk = 0; blk < 6; blk++) {
                uint32_t eh[4], el[4];
#pragma unroll
                for (int sub = 0; sub < 2; sub++) {
                    int ch = 2 * blk + sub;
                    uint32_t koff = (uint32_t)(8 * ch + r0) * 48 + 4 * m4;
                    uint32_t kb0 = *(const uint32_t*)(wb + O_K + koff);
                    uint32_t kb1 = *(const uint32_t*)(wb + O_K + koff + 16);
                    float S[4] = {0.f, 0.f, 0.f, 0.f};
                    mma_k16(S, qa, kb0, kb1);   // qh*kh + ql*kh + qh*kl
                    float e0 = ex2f(S[0]), e1 = ex2f(S[1]);
                    float e2 = ex2f(S[2]), e3 = ex2f(S[3]);
                    s_lo += e0 + e1;
                    s_hi += e2 + e3;
                    uint32_t sh0 = bpack(e0, e1), sh1 = bpack(e2, e3);
                    eh[2 * sub]     = sh0;
                    eh[2 * sub + 1] = sh1;
                    el[2 * sub]     = bpack(e0 - blo(sh0), e1 - bhi(sh0));
                    el[2 * sub + 1] = bpack(e2 - blo(sh1), e3 - bhi(sh1));
                }
                uint32_t voff = (uint32_t)r0 * 208 + 32 * blk + 4 * m4;
                uint32_t vh0 = *(const uint32_t*)(wb + O_VH + voff);
                uint32_t vh1 = *(const uint32_t*)(wb + O_VH + voff + 16);
                uint32_t vl0 = *(const uint32_t*)(wb + O_VL + voff);
                uint32_t vl1 = *(const uint32_t*)(wb + O_VL + voff + 16);
                mma_k16(accA, eh, vh0, vh1);
                mma_k16(accB, el, vh0, vh1);
                mma_k16(accB, eh, vl0, vl1);
            }

            s_lo += __shfl_xor_sync(0xffffffffu, s_lo, 1);
            s_lo += __shfl_xor_sync(0xffffffffu, s_lo, 2);
            s_hi += __shfl_xor_sync(0xffffffffu, s_hi, 1);
            s_hi += __shfl_xor_sync(0xffffffffu, s_hi, 2);
            float rl = rcpf(s_lo), rh = rcpf(s_hi);

            int i0 = 16 * t + r0;
            scr[d0 * 96 + i0]           = __float2half_rn((accA[0] + accB[0]) * rl * ao0 + bo0);
            scr[(d0 + 1) * 96 + i0]     = __float2half_rn((accA[1] + accB[1]) * rl * ao1 + bo1);
            scr[d0 * 96 + i0 + 8]       = __float2half_rn((accA[2] + accB[2]) * rh * ao0 + bo0);
            scr[(d0 + 1) * 96 + i0 + 8] = __float2half_rn((accA[3] + accB[3]) * rh * ao1 + bo1);
        }
    }
}

// Permute scr[(nt*64+hs)*6144 + d*96 + cl] (fp16) -> out[((nt*96+cl)*64 + d)*64 + hs]
extern "C" __global__ void __launch_bounds__(256)
attn_transpose_kernel(float* __restrict__ out) {
    __shared__ float tile[64 * 97];
    const int nt = blockIdx.x >> 6;
    const int d  = blockIdx.x & 63;

    const __half* src = g_scratch + (size_t)nt * 393216 + (size_t)d * 96;
#pragma unroll
    for (int u = 0; u < 3; u++) {
        int idx = threadIdx.x + 256 * u;
        int h = idx / 12, c8 = idx % 12;
        uint4 raw = *(const uint4*)(src + (size_t)h * 6144 + c8 * 8);
        const __half2* hp = (const __half2*)&raw;
        float* dst = &tile[h * 97 + c8 * 8];
#pragma unroll
        for (int e = 0; e < 4; e++) {
            float2 f = __half22float2(hp[e]);
            dst[2 * e]     = f.x;
            dst[2 * e + 1] = f.y;
        }
    }
    __syncthreads();

    float* dst = out + (size_t)nt * 393216 + (size_t)d * 64;
#pragma unroll
    for (int u = 0; u < 24; u++) {
        int idx = threadIdx.x + 256 * u;
        int cl = idx >> 6, h = idx & 63;
        dst[(size_t)cl * 4096 + h] = tile[h * 97 + cl];
    }
}

extern "C" void kernel_launch(void* const* d_in, const int* in_sizes, int n_in,
                              void* d_out, int out_size) {
    const float* x   = (const float*)d_in[0];
    const float* wq  = (const float*)d_in[1];
    const float* qg  = (const float*)d_in[2];
    const float* qb  = (const float*)d_in[3];
    const float* qm  = (const float*)d_in[4];
    const float* qv  = (const float*)d_in[5];
    const float* sg  = (const float*)d_in[6];
    const float* sb  = (const float*)d_in[7];
    const float* smn = (const float*)d_in[8];
    const float* svr = (const float*)d_in[9];
    const float* og  = (const float*)d_in[10];
    const float* ob  = (const float*)d_in[11];
    const float* om  = (const float*)d_in[12];
    const float* ov  = (const float*)d_in[13];
    float* out = (float*)d_out;

    cudaFuncSetAttribute(attn_fused_kernel,
                         cudaFuncAttributeMaxDynamicSharedMemorySize, SMEM_BYTES);

    attn_fused_kernel<<<2048, 256, SMEM_BYTES>>>(x, wq, qg, qb, qm, qv, sg, sb,
                                                 smn, svr, og, ob, om, ov);
    attn_transpose_kernel<<<2048, 256>>>(out);
}

// round 11
// speedup vs baseline: 1.2490x; 1.0322x over previous
#include <cuda_runtime.h>
#include <cuda_bf16.h>
#include <cuda_fp16.h>
#include <cstdint>

// NT=32, HS=64, WS=64 (K), CL=96 (l/j), OD=128 (o), G=8
// b = nt*64 + hs in [0,2048). One problem per CTA.

__device__ __align__(16) __half g_scratch[2048 * 64 * 96];  // scr[b*6144 + d*96 + cl]

__device__ __forceinline__ float ex2f(float x) {
    float r;
    asm("ex2.approx.f32 %0, %1;" : "=f"(r) : "f"(x));
    return r;
}
__device__ __forceinline__ float rcpf(float x) {
    float r;
    asm("rcp.approx.f32 %0, %1;" : "=f"(r) : "f"(x));
    return r;
}

__device__ __forceinline__ void mma_k16(float* d, const uint32_t* a,
                                        uint32_t b0, uint32_t b1) {
    asm volatile(
        "mma.sync.aligned.m16n8k16.row.col.f32.bf16.bf16.f32 "
        "{%0,%1,%2,%3}, {%4,%5,%6,%7}, {%8,%9}, {%0,%1,%2,%3};"
        : "+f"(d[0]), "+f"(d[1]), "+f"(d[2]), "+f"(d[3])
        : "r"(a[0]), "r"(a[1]), "r"(a[2]), "r"(a[3]), "r"(b0), "r"(b1));
}

__device__ __forceinline__ uint32_t bpack(float lo, float hi) {
    __nv_bfloat162 t = __float22bfloat162_rn(make_float2(lo, hi));
    return *(uint32_t*)&t;
}
__device__ __forceinline__ float blo(uint32_t hw) {
    return __uint_as_float(hw << 16);
}
__device__ __forceinline__ float bhi(uint32_t hw) {
    return __uint_as_float(hw & 0xFFFF0000u);
}

// split float4 into bf16-high / bf16-low, store 8B to each buffer
__device__ __forceinline__ void split8(char* hb, char* lb, uint32_t off, float4 v) {
    __nv_bfloat162 h0 = __float22bfloat162_rn(make_float2(v.x, v.y));
    __nv_bfloat162 h1 = __float22bfloat162_rn(make_float2(v.z, v.w));
    float2 f0 = __bfloat1622float2(h0), f1 = __bfloat1622float2(h1);
    __nv_bfloat162 l0 = __float22bfloat162_rn(make_float2(v.x - f0.x, v.y - f0.y));
    __nv_bfloat162 l1 = __float22bfloat162_rn(make_float2(v.z - f1.x, v.w - f1.y));
    uint2 hv, lv;
    hv.x = *(uint32_t*)&h0; hv.y = *(uint32_t*)&h1;
    lv.x = *(uint32_t*)&l0; lv.y = *(uint32_t*)&l1;
    *(uint2*)(hb + off) = hv;
    *(uint2*)(lb + off) = lv;
}

// ---------------- shared memory layout ----------------
// Phase 1 (QKV GEMM operands; rows stride 144B). Dead after MMA barrier.
#define OFF_AH 0        // Wh: 128 x 144B
#define OFF_AL 18432    // Wl
#define OFF_XH 36864    // Xh: 96 x 144B
#define OFF_XL 50688    // Xl              (end 64512)
// Phase 2: per-warp attention buffers (alias phase 1), base w*PWB:
//   Q: 96 rows x 48B; 16 bf16 slots = [qh(c0..3) | ql(c0..3) | qh(c0..3) | 0]
//   K: 96 rows x 48B; slots = [kh | kh | kl | 0]
//   VH/VL: 8 c-rows x 208B of bf16 over j (96 used)
#define PWB  12544
#define O_Q  0
#define O_K  4608
#define O_VH 9216
#define O_VL 10880      // end 12544; x8 warps = 100352
// coefficients, float indices from smem base (byte 100352+):
#define CAQ 25088
#define CBQ 25216
#define CAS 25344
#define CAO 25352
#define CBO 25416
#define SMEM_BYTES 101920

extern "C" __global__ void __launch_bounds__(256, 2)
attn_fused_kernel(const float* __restrict__ x, const float* __restrict__ w_qkv,
                  const float* __restrict__ qg, const float* __restrict__ qb,
                  const float* __restrict__ qm, const float* __restrict__ qv,
                  const float* __restrict__ sg, const float* __restrict__ sb,
                  const float* __restrict__ smn, const float* __restrict__ svr,
                  const float* __restrict__ og, const float* __restrict__ ob,
                  const float* __restrict__ om, const float* __restrict__ ov) {
    extern __shared__ __align__(16) char smemc[];
    float* smem = (float*)smemc;
    const int tid  = threadIdx.x;
    const int lane = tid & 31;
    const int w    = tid >> 5;
    const int b    = blockIdx.x;
    const int nt   = b >> 6;
    const int hs   = b & 63;
    const int r0   = lane >> 2;   // 0..7
    const int m4   = lane & 3;    // 0..3

    // ---- BN coefficient precompute ----
    if (tid < 128) {
        float a = qg[tid] * rsqrtf(qv[tid] + 1e-5f);
        smem[CAQ + tid] = a;
        smem[CBQ + tid] = qb[tid] - qm[tid] * a;
    }
    if (tid < 64) {
        float a = og[tid] * rsqrtf(ov[tid] + 1e-5f);
        smem[CAO + tid] = a;
        smem[CBO + tid] = ob[tid] - om[tid] * a;
    }
    if (tid < 8) {
        smem[CAS + tid] = sg[tid] * rsqrtf(svr[tid] + 1e-5f);
        (void)sb; (void)smn;  // sim BN bias cancels inside softmax
    }

    // ---- operand prep: W split (A, 128 rows(o) x 64 bf16(i)) ----
#pragma unroll
    for (int u = 0; u < 8; u++) {
        int idx4 = tid + 256 * u;
        int o = idx4 >> 4, i4 = idx4 & 15;
        float4 v = *(const float4*)(w_qkv + idx4 * 4);
        split8(smemc + OFF_AH, smemc + OFF_AL, o * 144 + i4 * 8, v);
    }
    // ---- operand prep: X split (B, 96 rows(l) x 64 bf16(i)) ----
    {
        const float* xbase = x + (size_t)nt * 393216 + (size_t)hs * 64;
#pragma unroll
        for (int u = 0; u < 6; u++) {
            int idx = tid + 256 * u;
            int i4 = idx & 15, l = idx >> 4;
            float4 v = *(const float4*)(xbase + (size_t)l * 4096 + i4 * 4);
            split8(smemc + OFF_XH, smemc + OFF_XL, l * 144 + i4 * 8, v);
        }
    }
    __syncthreads();

    // ---- tensor-core QKV GEMM: warp w owns rows o in [16w, 16w+16) ----
    float d[12][4];
#pragma unroll
    for (int p = 0; p < 12; p++)
#pragma unroll
        for (int q = 0; q < 4; q++) d[p][q] = 0.f;
    {
        const int qk2 = m4 * 4;
        uint32_t ah[4][4];
#pragma unroll
        for (int k = 0; k < 4; k++) {
            uint32_t off = (uint32_t)(16 * w + r0) * 144 + 32 * k + qk2;
            ah[k][0] = *(const uint32_t*)(smemc + OFF_AH + off);
            ah[k][1] = *(const uint32_t*)(smemc + OFF_AH + off + 8 * 144);
            ah[k][2] = *(const uint32_t*)(smemc + OFF_AH + off + 16);
            ah[k][3] = *(const uint32_t*)(smemc + OFF_AH + off + 8 * 144 + 16);
        }
#pragma unroll
        for (int k = 0; k < 4; k++)
#pragma unroll
            for (int p = 0; p < 6; p++) {
                uint32_t boff = (uint32_t)(16 * p + r0) * 144 + 32 * k + qk2;
                uint32_t b0 = *(const uint32_t*)(smemc + OFF_XH + boff);
                uint32_t b1 = *(const uint32_t*)(smemc + OFF_XH + boff + 16);
                uint32_t b2 = *(const uint32_t*)(smemc + OFF_XH + boff + 8 * 144);
                uint32_t b3 = *(const uint32_t*)(smemc + OFF_XH + boff + 8 * 144 + 16);
                mma_k16(d[2 * p],     ah[k], b0, b1);
                mma_k16(d[2 * p + 1], ah[k], b2, b3);
            }
#pragma unroll
        for (int k = 0; k < 4; k++)
#pragma unroll
            for (int p = 0; p < 6; p++) {
                uint32_t boff = (uint32_t)(16 * p + r0) * 144 + 32 * k + qk2;
                uint32_t b0 = *(const uint32_t*)(smemc + OFF_XL + boff);
                uint32_t b1 = *(const uint32_t*)(smemc + OFF_XL + boff + 16);
                uint32_t b2 = *(const uint32_t*)(smemc + OFF_XL + boff + 8 * 144);
                uint32_t b3 = *(const uint32_t*)(smemc + OFF_XL + boff + 8 * 144 + 16);
                mma_k16(d[2 * p],     ah[k], b0, b1);
                mma_k16(d[2 * p + 1], ah[k], b2, b3);
            }
#pragma unroll
        for (int k = 0; k < 4; k++) {
            uint32_t off = (uint32_t)(16 * w + r0) * 144 + 32 * k + qk2;
            uint32_t al[4];
            al[0] = *(const uint32_t*)(smemc + OFF_AL + off);
            al[1] = *(const uint32_t*)(smemc + OFF_AL + off + 8 * 144);
            al[2] = *(const uint32_t*)(smemc + OFF_AL + off + 16);
            al[3] = *(const uint32_t*)(smemc + OFF_AL + off + 8 * 144 + 16);
#pragma unroll
            for (int p = 0; p < 6; p++) {
                uint32_t boff = (uint32_t)(16 * p + r0) * 144 + 32 * k + qk2;
                uint32_t b0 = *(const uint32_t*)(smemc + OFF_XH + boff);
                uint32_t b1 = *(const uint32_t*)(smemc + OFF_XH + boff + 16);
                uint32_t b2 = *(const uint32_t*)(smemc + OFF_XH + boff + 8 * 144);
                uint32_t b3 = *(const uint32_t*)(smemc + OFF_XH + boff + 8 * 144 + 16);
                mma_k16(d[2 * p],     al, b0, b1);
                mma_k16(d[2 * p + 1], al, b2, b3);
            }
        }
    }
    __syncthreads();   // operand reads done; per-warp buffers may alias now

    char* wb = smemc + w * PWB;

    // ---- zero the k-slot padding (bytes 24..31 of each Q/K row) ----
#pragma unroll
    for (int u = 0; u < 3; u++) {
        int row = lane + 32 * u;
        *(uint64_t*)(wb + O_Q + row * 48 + 24) = 0ull;
        *(uint64_t*)(wb + O_K + row * 48 + 24) = 0ull;
    }

    // ---- epilogue: BN; q/k/v into attention operand buffers ----
    {
        const float sc = smem[CAS + w] * 1.4426950408889634f;  // ag/ln2
        const int o = 16 * w + r0;
        float A, B;
        if (r0 < 4) { A = smem[CAQ + o] * sc; B = smem[CBQ + o] * sc; }
        else        { A = smem[CAQ + o];      B = smem[CBQ + o]; }
        const float av = smem[CAQ + o + 8], bv = smem[CBQ + o + 8];
#pragma unroll
        for (int p = 0; p < 12; p++) {
            int l0 = 8 * p + 2 * m4;
            float v0 = d[p][0] * A + B, v1 = d[p][1] * A + B;
            __nv_bfloat16 h0 = __float2bfloat16_rn(v0);
            __nv_bfloat16 h1 = __float2bfloat16_rn(v1);
            __nv_bfloat16 g0 = __float2bfloat16_rn(v0 - __bfloat162float(h0));
            __nv_bfloat16 g1 = __float2bfloat16_rn(v1 - __bfloat162float(h1));
            if (r0 < 4) {
                int c = r0;
                char* q0p = wb + O_Q + l0 * 48;
                char* q1p = q0p + 48;
                *(__nv_bfloat16*)(q0p + 2 * c)       = h0;
                *(__nv_bfloat16*)(q0p + 2 * (8 + c)) = h0;
                *(__nv_bfloat16*)(q0p + 2 * (4 + c)) = g0;
                *(__nv_bfloat16*)(q1p + 2 * c)       = h1;
                *(__nv_bfloat16*)(q1p + 2 * (8 + c)) = h1;
                *(__nv_bfloat16*)(q1p + 2 * (4 + c)) = g1;
            } else {
                int c = r0 - 4;
                char* k0p = wb + O_K + l0 * 48;
                char* k1p = k0p + 48;
                *(__nv_bfloat16*)(k0p + 2 * c)       = h0;
                *(__nv_bfloat16*)(k0p + 2 * (4 + c)) = h0;
                *(__nv_bfloat16*)(k0p + 2 * (8 + c)) = g0;
                *(__nv_bfloat16*)(k1p + 2 * c)       = h1;
                *(__nv_bfloat16*)(k1p + 2 * (4 + c)) = h1;
                *(__nv_bfloat16*)(k1p + 2 * (8 + c)) = g1;
            }
            float vb0 = d[p][2] * av + bv, vb1 = d[p][3] * av + bv;
            uint32_t hv = bpack(vb0, vb1);
            uint32_t lv = bpack(vb0 - blo(hv), vb1 - bhi(hv));
            *(uint32_t*)(wb + O_VH + r0 * 208 + l0 * 2) = hv;
            *(uint32_t*)(wb + O_VL + r0 * 208 + l0 * 2) = lv;
        }
    }
    __syncwarp();   // buffers are warp-private

    // ---- HMMA attention: all-k16, two m-tiles interleaved per iteration ----
    // k/v fragment loads are shared between the paired tiles; doubled chains
    // hide the S -> ex2 -> pack -> SV latency.
    {
        __half* scr = &g_scratch[(size_t)b * 6144];
        const int d0 = 8 * w + 2 * m4;
        const float ao0 = smem[CAO + d0],     bo0 = smem[CBO + d0];
        const float ao1 = smem[CAO + d0 + 1], bo1 = smem[CBO + d0 + 1];

#pragma unroll 1
        for (int tp = 0; tp < 3; tp++) {
            uint32_t qa0[4], qa1[4];
            {
                uint32_t qoff = (uint32_t)(32 * tp + r0) * 48 + 4 * m4;
                qa0[0] = *(const uint32_t*)(wb + O_Q + qoff);
                qa0[1] = *(const uint32_t*)(wb + O_Q + qoff + 8 * 48);
                qa0[2] = *(const uint32_t*)(wb + O_Q + qoff + 16);
                qa0[3] = *(const uint32_t*)(wb + O_Q + qoff + 8 * 48 + 16);
                uint32_t qoff1 = qoff + 16 * 48;
                qa1[0] = *(const uint32_t*)(wb + O_Q + qoff1);
                qa1[1] = *(const uint32_t*)(wb + O_Q + qoff1 + 8 * 48);
                qa1[2] = *(const uint32_t*)(wb + O_Q + qoff1 + 16);
                qa1[3] = *(const uint32_t*)(wb + O_Q + qoff1 + 8 * 48 + 16);
            }
            float a0A[4] = {0.f, 0.f, 0.f, 0.f}, a0B[4] = {0.f, 0.f, 0.f, 0.f};
            float a1A[4] = {0.f, 0.f, 0.f, 0.f}, a1B[4] = {0.f, 0.f, 0.f, 0.f};
            float s0_lo = 0.f, s0_hi = 0.f, s1_lo = 0.f, s1_hi = 0.f;

#pragma unroll 2
            for (int blk = 0; blk < 6; blk++) {
                uint32_t eh0[4], el0[4], eh1[4], el1[4];
#pragma unroll
                for (int sub = 0; sub < 2; sub++) {
                    int ch = 2 * blk + sub;
                    uint32_t koff = (uint32_t)(8 * ch + r0) * 48 + 4 * m4;
                    uint32_t kb0 = *(const uint32_t*)(wb + O_K + koff);
                    uint32_t kb1 = *(const uint32_t*)(wb + O_K + koff + 16);

                    float S0[4] = {0.f, 0.f, 0.f, 0.f};
                    float S1[4] = {0.f, 0.f, 0.f, 0.f};
                    mma_k16(S0, qa0, kb0, kb1);   // qh*kh + ql*kh + qh*kl
                    mma_k16(S1, qa1, kb0, kb1);

                    float e00 = ex2f(S0[0]), e01 = ex2f(S0[1]);
                    float e02 = ex2f(S0[2]), e03 = ex2f(S0[3]);
                    s0_lo += e00 + e01;
                    s0_hi += e02 + e03;
                    uint32_t p00 = bpack(e00, e01), p01 = bpack(e02, e03);
                    eh0[2 * sub]     = p00;
                    eh0[2 * sub + 1] = p01;
                    el0[2 * sub]     = bpack(e00 - blo(p00), e01 - bhi(p00));
                    el0[2 * sub + 1] = bpack(e02 - blo(p01), e03 - bhi(p01));

                    float e10 = ex2f(S1[0]), e11 = ex2f(S1[1]);
                    float e12 = ex2f(S1[2]), e13 = ex2f(S1[3]);
                    s1_lo += e10 + e11;
                    s1_hi += e12 + e13;
                    uint32_t p10 = bpack(e10, e11), p11 = bpack(e12, e13);
                    eh1[2 * sub]     = p10;
                    eh1[2 * sub + 1] = p11;
                    el1[2 * sub]     = bpack(e10 - blo(p10), e11 - bhi(p10));
                    el1[2 * sub + 1] = bpack(e12 - blo(p11), e13 - bhi(p11));
                }
                uint32_t voff = (uint32_t)r0 * 208 + 32 * blk + 4 * m4;
                uint32_t vh0 = *(const uint32_t*)(wb + O_VH + voff);
                uint32_t vh1 = *(const uint32_t*)(wb + O_VH + voff + 16);
                uint32_t vl0 = *(const uint32_t*)(wb + O_VL + voff);
                uint32_t vl1 = *(const uint32_t*)(wb + O_VL + voff + 16);
                mma_k16(a0A, eh0, vh0, vh1);
                mma_k16(a1A, eh1, vh0, vh1);
                mma_k16(a0B, el0, vh0, vh1);
                mma_k16(a1B, el1, vh0, vh1);
                mma_k16(a0B, eh0, vl0, vl1);
                mma_k16(a1B, eh1, vl0, vl1);
            }

            s0_lo += __shfl_xor_sync(0xffffffffu, s0_lo, 1);
            s0_lo += __shfl_xor_sync(0xffffffffu, s0_lo, 2);
            s0_hi += __shfl_xor_sync(0xffffffffu, s0_hi, 1);
            s0_hi += __shfl_xor_sync(0xffffffffu, s0_hi, 2);
            s1_lo += __shfl_xor_sync(0xffffffffu, s1_lo, 1);
            s1_lo += __shfl_xor_sync(0xffffffffu, s1_lo, 2);
            s1_hi += __shfl_xor_sync(0xffffffffu, s1_hi, 1);
            s1_hi += __shfl_xor_sync(0xffffffffu, s1_hi, 2);
            float r0l = rcpf(s0_lo), r0h = rcpf(s0_hi);
            float r1l = rcpf(s1_lo), r1h = rcpf(s1_hi);

            int i0 = 32 * tp + r0;
            scr[d0 * 96 + i0]            = __float2half_rn((a0A[0] + a0B[0]) * r0l * ao0 + bo0);
            scr[(d0 + 1) * 96 + i0]      = __float2half_rn((a0A[1] + a0B[1]) * r0l * ao1 + bo1);
            scr[d0 * 96 + i0 + 8]        = __float2half_rn((a0A[2] + a0B[2]) * r0h * ao0 + bo0);
            scr[(d0 + 1) * 96 + i0 + 8]  = __float2half_rn((a0A[3] + a0B[3]) * r0h * ao1 + bo1);
            int i1 = i0 + 16;
            scr[d0 * 96 + i1]            = __float2half_rn((a1A[0] + a1B[0]) * r1l * ao0 + bo0);
            scr[(d0 + 1) * 96 + i1]      = __float2half_rn((a1A[1] + a1B[1]) * r1l * ao1 + bo1);
            scr[d0 * 96 + i1 + 8]        = __float2half_rn((a1A[2] + a1B[2]) * r1h * ao0 + bo0);
            scr[(d0 + 1) * 96 + i1 + 8]  = __float2half_rn((a1A[3] + a1B[3]) * r1h * ao1 + bo1);
        }
    }
}

// Permute scr[(nt*64+hs)*6144 + d*96 + cl] (fp16) -> out[((nt*96+cl)*64 + d)*64 + hs]
extern "C" __global__ void __launch_bounds__(256)
attn_transpose_kernel(float* __restrict__ out) {
    __shared__ float tile[64 * 97];
    const int nt = blockIdx.x >> 6;
    const int d  = blockIdx.x & 63;

    const __half* src = g_scratch + (size_t)nt * 393216 + (size_t)d * 96;
#pragma unroll
    for (int u = 0; u < 3; u++) {
        int idx = threadIdx.x + 256 * u;
        int h = idx / 12, c8 = idx % 12;
        uint4 raw = *(const uint4*)(src + (size_t)h * 6144 + c8 * 8);
        const __half2* hp = (const __half2*)&raw;
        float* dst = &tile[h * 97 + c8 * 8];
#pragma unroll
        for (int e = 0; e < 4; e++) {
            float2 f = __half22float2(hp[e]);
            dst[2 * e]     = f.x;
            dst[2 * e + 1] = f.y;
        }
    }
    __syncthreads();

    float* dst = out + (size_t)nt * 393216 + (size_t)d * 64;
#pragma unroll
    for (int u = 0; u < 24; u++) {
        int idx = threadIdx.x + 256 * u;
        int cl = idx >> 6, h = idx & 63;
        dst[(size_t)cl * 4096 + h] = tile[h * 97 + cl];
    }
}

extern "C" void kernel_launch(void* const* d_in, const int* in_sizes, int n_in,
                              void* d_out, int out_size) {
    const float* x   = (const float*)d_in[0];
    const float* wq  = (const float*)d_in[1];
    const float* qg  = (const float*)d_in[2];
    const float* qb  = (const float*)d_in[3];
    const float* qm  = (const float*)d_in[4];
    const float* qv  = (const float*)d_in[5];
    const float* sg  = (const float*)d_in[6];
    const float* sb  = (const float*)d_in[7];
    const float* smn = (const float*)d_in[8];
    const float* svr = (const float*)d_in[9];
    const float* og  = (const float*)d_in[10];
    const float* ob  = (const float*)d_in[11];
    const float* om  = (const float*)d_in[12];
    const float* ov  = (const float*)d_in[13];
    float* out = (float*)d_out;

    cudaFuncSetAttribute(attn_fused_kernel,
                         cudaFuncAttributeMaxDynamicSharedMemorySize, SMEM_BYTES);

    attn_fused_kernel<<<2048, 256, SMEM_BYTES>>>(x, wq, qg, qb, qm, qv, sg, sb,
                                                 smn, svr, og, ob, om, ov);
    attn_transpose_kernel<<<2048, 256>>>(out);
}